// round 5
// baseline (speedup 1.0000x reference)
#include <cuda_runtime.h>
#include <cuda_fp16.h>
#include <cstdint>

#define E_ 8
#define H_ 2048
#define I_ 4096
#define T_ 1024

// ---------------- scratch: 96 MB total — R1's PROVEN static footprint ------
__device__ __half g_xh[(size_t)E_ * T_ * H_];        // fp16 activations  (32 MB)
__device__ __half g_inter[(size_t)E_ * T_ * I_];     // fp16 intermediate (64 MB)

// ---------------- helpers ----------------
// Exact e2m1 decode (bit-identical to the R1 LUT values): codes 0..7 map to
// {0,.5,1,1.5,2,3,4,6}, bit3 = sign.
__device__ __forceinline__ float fp4f(int c) {
    int h = c & 7;
    int bits = (h < 2) ? h * 0x3F000000 : (((126 + (h >> 1)) << 23) | ((h & 1) << 22));
    bits |= (c & 8) << 28;
    return __int_as_float(bits);
}

__device__ __forceinline__ uint32_t pack2(float a, float b) {
    __half2 t = __floats2half2_rn(a, b);
    return *reinterpret_cast<uint32_t*>(&t);
}

__device__ __forceinline__ void mma16816(float& d0, float& d1, float& d2, float& d3,
                                         uint32_t a0, uint32_t a1, uint32_t a2, uint32_t a3,
                                         uint32_t b0, uint32_t b1) {
    asm volatile(
        "mma.sync.aligned.m16n8k16.row.col.f32.f16.f16.f32 "
        "{%0,%1,%2,%3},{%4,%5,%6,%7},{%8,%9},{%0,%1,%2,%3};\n"
        : "+f"(d0), "+f"(d1), "+f"(d2), "+f"(d3)
        : "r"(a0), "r"(a1), "r"(a2), "r"(a3), "r"(b0), "r"(b1));
}

__device__ __forceinline__ float silu_f(float v) { return v / (1.f + __expf(-v)); }

// ---------------------------------------------------------------------------
// Kernel 0: fp32 -> fp16 activation convert (verbatim R1, passing)
// ---------------------------------------------------------------------------
__global__ void convert_x_kernel(const float* __restrict__ x) {
    int i = (blockIdx.x * blockDim.x + threadIdx.x) * 4;
    float4 v = *reinterpret_cast<const float4*>(x + i);
    __half2* o = reinterpret_cast<__half2*>(g_xh + i);
    o[0] = __floats2half2_rn(v.x, v.y);
    o[1] = __floats2half2_rn(v.z, v.w);
}

// ---------------------------------------------------------------------------
// Kernel 1: gemm1 (x @ Wgu) + fused SiLU-gate, in-loop NVFP4 dequant.
// BM=256 tokens x BN=32 (gate col n and up col I_+n), BK=64.
// 256 threads = 8 warps (wm 0..3 x wn 0..1). Warp tile 64x16 (gate) + 64x16 (up).
// Smem: As 256x72 + Bg 32x72 + Bu 32x72 halves = 46,080 B (static, <48 KB).
// Grid: x = m-tile (fastest) -> weight-slab L2 reuse across the 4 m-tiles.
// ---------------------------------------------------------------------------
__global__ void __launch_bounds__(256) gemm1_silu_kernel(
    const int*   __restrict__ gup,     // [E, H/2, 2I] int32 (1 byte each)
    const float* __restrict__ gus,     // [E, H/16, 2I]
    const float* __restrict__ pgs)     // scalar gscale
{
    const int e   = blockIdx.z;
    const int bm0 = blockIdx.x * 256;
    const int n0  = blockIdx.y * 32;
    const float gscale = __ldg(pgs);

    const int tid  = threadIdx.x;
    const int lane = tid & 31;
    const int wid  = tid >> 5;
    const int g    = lane >> 2;
    const int tg   = lane & 3;
    const int wm   = wid & 3;       // 0..3 (64 rows each)
    const int wn   = wid >> 2;      // 0..1 (16 cols each)

    __shared__ __half As[256 * 72];
    __shared__ __half Bg[32 * 72];
    __shared__ __half Bu[32 * 72];

    float accg[4][2][4], accu[4][2][4];
#pragma unroll
    for (int a = 0; a < 4; a++)
#pragma unroll
        for (int b = 0; b < 2; b++)
#pragma unroll
            for (int c = 0; c < 4; c++) { accg[a][b][c] = 0.f; accu[a][b][c] = 0.f; }

    const __half* xg = g_xh + (size_t)(e * T_ + bm0) * H_;

    for (int k0 = 0; k0 < H_; k0 += 64) {
        // ---- stage A tile: 2048 uint4, 8/thread, fully coalesced ----
#pragma unroll
        for (int i = 0; i < 8; i++) {
            const int u = tid + 256 * i;
            const int row = u >> 3, seg = (u & 7) * 8;
            *reinterpret_cast<uint4*>(As + row * 72 + seg) =
                *reinterpret_cast<const uint4*>(xg + (size_t)row * H_ + k0 + seg);
        }
        // ---- stage B tiles: inline dequant, 32 kp x 32 cols, 4/thread ----
#pragma unroll
        for (int i = 0; i < 4; i++) {
            const int id  = tid + 256 * i;
            const int col = id & 31;         // lanes -> contiguous cols (coalesced)
            const int kp  = id >> 5;         // 0..31
            const int kb  = (k0 >> 4) + (kp >> 3);
            const size_t sidx = ((size_t)e * (H_ / 16) + kb) * (2 * I_) + n0 + col;
            const float sg = __ldg(gus + sidx)      * gscale;
            const float su = __ldg(gus + sidx + I_) * gscale;
            const size_t pidx = ((size_t)e * (H_ / 2) + (k0 >> 1) + kp) * (2 * I_) + n0 + col;
            const int vg = __ldg(gup + pidx);
            const int vu = __ldg(gup + pidx + I_);
            *reinterpret_cast<uint32_t*>(Bg + col * 72 + 2 * kp) =
                pack2(fp4f(vg & 15) * sg, fp4f((vg >> 4) & 15) * sg);
            *reinterpret_cast<uint32_t*>(Bu + col * 72 + 2 * kp) =
                pack2(fp4f(vu & 15) * su, fp4f((vu >> 4) & 15) * su);
        }
        __syncthreads();

        // ---- compute: 4 k16 steps (R1-verified fragment scheme) ----
#pragma unroll
        for (int kk = 0; kk < 4; kk++) {
            const int cc = kk * 16 + 2 * tg;
            uint32_t a[4][4];
#pragma unroll
            for (int mi = 0; mi < 4; mi++) {
                const int r = wm * 64 + mi * 16 + g;
                a[mi][0] = *reinterpret_cast<const uint32_t*>(As + r * 72 + cc);
                a[mi][1] = *reinterpret_cast<const uint32_t*>(As + (r + 8) * 72 + cc);
                a[mi][2] = *reinterpret_cast<const uint32_t*>(As + r * 72 + cc + 8);
                a[mi][3] = *reinterpret_cast<const uint32_t*>(As + (r + 8) * 72 + cc + 8);
            }
#pragma unroll
            for (int ni = 0; ni < 2; ni++) {
                const int nb = wn * 16 + ni * 8 + g;
                const uint32_t bg0 = *reinterpret_cast<const uint32_t*>(Bg + nb * 72 + cc);
                const uint32_t bg1 = *reinterpret_cast<const uint32_t*>(Bg + nb * 72 + cc + 8);
                const uint32_t bu0 = *reinterpret_cast<const uint32_t*>(Bu + nb * 72 + cc);
                const uint32_t bu1 = *reinterpret_cast<const uint32_t*>(Bu + nb * 72 + cc + 8);
#pragma unroll
                for (int mi = 0; mi < 4; mi++) {
                    mma16816(accg[mi][ni][0], accg[mi][ni][1], accg[mi][ni][2], accg[mi][ni][3],
                             a[mi][0], a[mi][1], a[mi][2], a[mi][3], bg0, bg1);
                    mma16816(accu[mi][ni][0], accu[mi][ni][1], accu[mi][ni][2], accu[mi][ni][3],
                             a[mi][0], a[mi][1], a[mi][2], a[mi][3], bu0, bu1);
                }
            }
        }
        __syncthreads();
    }

    // ---- epilogue: inter = up * silu(gate), fp16 store (R1 scheme) ----
#pragma unroll
    for (int mi = 0; mi < 4; mi++) {
        const int r0 = bm0 + wm * 64 + mi * 16 + g;
#pragma unroll
        for (int ni = 0; ni < 2; ni++) {
            const int c0 = n0 + wn * 16 + ni * 8 + 2 * tg;
            const float i0 = accu[mi][ni][0] * silu_f(accg[mi][ni][0]);
            const float i1 = accu[mi][ni][1] * silu_f(accg[mi][ni][1]);
            const float i2 = accu[mi][ni][2] * silu_f(accg[mi][ni][2]);
            const float i3 = accu[mi][ni][3] * silu_f(accg[mi][ni][3]);
            *reinterpret_cast<__half2*>(g_inter + (size_t)(e * T_ + r0) * I_ + c0)
                = __floats2half2_rn(i0, i1);
            *reinterpret_cast<__half2*>(g_inter + (size_t)(e * T_ + r0 + 8) * I_ + c0)
                = __floats2half2_rn(i2, i3);
        }
    }
}

// ---------------------------------------------------------------------------
// Kernel 2: gemm2 (inter @ Wd) -> fp32 out, in-loop dequant.
// BM=256 x BN=64, BK=64. 8 warps (wm 0..3 x wn 0..1), warp tile 64x32.
// Smem: As 256x72 + Bs 64x72 halves = 46,080 B.
// ---------------------------------------------------------------------------
__global__ void __launch_bounds__(256) gemm2_kernel(
    const int*   __restrict__ dpk,     // [E, I/2, H] int32
    const float* __restrict__ dsc,     // [E, I/16, H]
    const float* __restrict__ pgs,     // scalar gscale
    float*       __restrict__ out)     // [E*T, H]
{
    const int e   = blockIdx.z;
    const int bm0 = blockIdx.x * 256;
    const int n0  = blockIdx.y * 64;
    const float gscale = __ldg(pgs);

    const int tid  = threadIdx.x;
    const int lane = tid & 31;
    const int wid  = tid >> 5;
    const int g    = lane >> 2;
    const int tg   = lane & 3;
    const int wm   = wid & 3;       // 0..3
    const int wn   = wid >> 2;      // 0..1 (32 cols each)

    __shared__ __half As[256 * 72];
    __shared__ __half Bs[64 * 72];

    float acc[4][4][4];
#pragma unroll
    for (int a = 0; a < 4; a++)
#pragma unroll
        for (int b = 0; b < 4; b++)
#pragma unroll
            for (int c = 0; c < 4; c++) acc[a][b][c] = 0.f;

    const __half* ag = g_inter + (size_t)(e * T_ + bm0) * I_;

    for (int k0 = 0; k0 < I_; k0 += 64) {
        // ---- stage A tile ----
#pragma unroll
        for (int i = 0; i < 8; i++) {
            const int u = tid + 256 * i;
            const int row = u >> 3, seg = (u & 7) * 8;
            *reinterpret_cast<uint4*>(As + row * 72 + seg) =
                *reinterpret_cast<const uint4*>(ag + (size_t)row * I_ + k0 + seg);
        }
        // ---- stage B tile: inline dequant, 32 kp x 64 cols, 8/thread ----
#pragma unroll
        for (int i = 0; i < 8; i++) {
            const int id  = tid + 256 * i;
            const int col = id & 63;
            const int kp  = id >> 6;         // 0..31
            const int kb  = (k0 >> 4) + (kp >> 3);
            const float s = __ldg(dsc + ((size_t)e * (I_ / 16) + kb) * H_ + n0 + col) * gscale;
            const int v = __ldg(dpk + ((size_t)e * (I_ / 2) + (k0 >> 1) + kp) * H_ + n0 + col);
            *reinterpret_cast<uint32_t*>(Bs + col * 72 + 2 * kp) =
                pack2(fp4f(v & 15) * s, fp4f((v >> 4) & 15) * s);
        }
        __syncthreads();

        // ---- compute ----
#pragma unroll
        for (int kk = 0; kk < 4; kk++) {
            const int cc = kk * 16 + 2 * tg;
            uint32_t a[4][4];
#pragma unroll
            for (int mi = 0; mi < 4; mi++) {
                const int r = wm * 64 + mi * 16 + g;
                a[mi][0] = *reinterpret_cast<const uint32_t*>(As + r * 72 + cc);
                a[mi][1] = *reinterpret_cast<const uint32_t*>(As + (r + 8) * 72 + cc);
                a[mi][2] = *reinterpret_cast<const uint32_t*>(As + r * 72 + cc + 8);
                a[mi][3] = *reinterpret_cast<const uint32_t*>(As + (r + 8) * 72 + cc + 8);
            }
#pragma unroll
            for (int ni = 0; ni < 4; ni++) {
                const int nb = wn * 32 + ni * 8 + g;
                const uint32_t b0 = *reinterpret_cast<const uint32_t*>(Bs + nb * 72 + cc);
                const uint32_t b1 = *reinterpret_cast<const uint32_t*>(Bs + nb * 72 + cc + 8);
#pragma unroll
                for (int mi = 0; mi < 4; mi++) {
                    mma16816(acc[mi][ni][0], acc[mi][ni][1], acc[mi][ni][2], acc[mi][ni][3],
                             a[mi][0], a[mi][1], a[mi][2], a[mi][3], b0, b1);
                }
            }
        }
        __syncthreads();
    }

    // ---- epilogue: fp32 stores ----
#pragma unroll
    for (int mi = 0; mi < 4; mi++) {
        const int r0 = bm0 + wm * 64 + mi * 16 + g;
#pragma unroll
        for (int ni = 0; ni < 4; ni++) {
            const int c0 = n0 + wn * 32 + ni * 8 + 2 * tg;
            *reinterpret_cast<float2*>(out + (size_t)(e * T_ + r0) * H_ + c0)
                = make_float2(acc[mi][ni][0], acc[mi][ni][1]);
            *reinterpret_cast<float2*>(out + (size_t)(e * T_ + r0 + 8) * H_ + c0)
                = make_float2(acc[mi][ni][2], acc[mi][ni][3]);
        }
    }
}

// ---------------------------------------------------------------------------
// Launch
// ---------------------------------------------------------------------------
extern "C" void kernel_launch(void* const* d_in, const int* in_sizes, int n_in,
                              void* d_out, int out_size) {
    const float* x   = (const float*)d_in[0];  // hidden_states
    const int*   gup = (const int*)  d_in[1];  // gate_up_packed
    const float* gus = (const float*)d_in[2];  // gate_up_scale
    const float* gug = (const float*)d_in[3];  // gate_up_gscale
    const int*   dpk = (const int*)  d_in[4];  // down_packed
    const float* dsc = (const float*)d_in[5];  // down_scale
    const float* dgs = (const float*)d_in[6];  // down_gscale
    float* out = (float*)d_out;

    convert_x_kernel<<<(E_ * T_ * H_) / 1024, 256>>>(x);

    // m-tile fastest (x) -> the 4 m-blocks sharing a weight slab co-resident
    gemm1_silu_kernel<<<dim3(T_ / 256, I_ / 32, E_), 256>>>(gup, gus, gug);
    gemm2_kernel<<<dim3(T_ / 256, H_ / 64, E_), 256>>>(dpk, dsc, dgs, out);
}

// round 6
// speedup vs baseline: 1.7720x; 1.7720x over previous
#include <cuda_runtime.h>
#include <cuda_fp16.h>
#include <cstdint>

#define E_ 8
#define H_ 2048
#define I_ 4096
#define T_ 1024

// ---------------- scratch: 96 MB total — proven static footprint ------------
__device__ __half g_xh[(size_t)E_ * T_ * H_];        // fp16 activations  (32 MB)
__device__ __half g_inter[(size_t)E_ * T_ * I_];     // fp16 intermediate (64 MB)

// ---------------- helpers ----------------
// Exact e2m1 decode (bit-identical to R1 LUT): codes 0..7 -> {0,.5,1,1.5,2,3,4,6},
// bit3 = sign.
__device__ __forceinline__ float fp4f(int c) {
    int h = c & 7;
    int bits = (h < 2) ? h * 0x3F000000 : (((126 + (h >> 1)) << 23) | ((h & 1) << 22));
    bits |= (c & 8) << 28;
    return __int_as_float(bits);
}

__device__ __forceinline__ uint32_t pack2(float a, float b) {
    __half2 t = __floats2half2_rn(a, b);
    return *reinterpret_cast<uint32_t*>(&t);
}

__device__ __forceinline__ void cpasync16(__half* dst, const __half* src) {
    uint32_t d = (uint32_t)__cvta_generic_to_shared(dst);
    asm volatile("cp.async.cg.shared.global [%0], [%1], 16;" :: "r"(d), "l"(src));
}
#define CP_COMMIT() asm volatile("cp.async.commit_group;")
#define CP_WAIT0()  asm volatile("cp.async.wait_group 0;")

__device__ __forceinline__ void mma16816(float& d0, float& d1, float& d2, float& d3,
                                         uint32_t a0, uint32_t a1, uint32_t a2, uint32_t a3,
                                         uint32_t b0, uint32_t b1) {
    asm volatile(
        "mma.sync.aligned.m16n8k16.row.col.f32.f16.f16.f32 "
        "{%0,%1,%2,%3},{%4,%5,%6,%7},{%8,%9},{%0,%1,%2,%3};\n"
        : "+f"(d0), "+f"(d1), "+f"(d2), "+f"(d3)
        : "r"(a0), "r"(a1), "r"(a2), "r"(a3), "r"(b0), "r"(b1));
}

__device__ __forceinline__ float silu_f(float v) { return v / (1.f + __expf(-v)); }

// smem row stride in halves (80 B): conflict-free for the fragment pattern.
#define STR 40

// ---------------------------------------------------------------------------
// Kernel 0: fp32 -> fp16 activation convert (verbatim R1, passing)
// ---------------------------------------------------------------------------
__global__ void convert_x_kernel(const float* __restrict__ x) {
    int i = (blockIdx.x * blockDim.x + threadIdx.x) * 4;
    float4 v = *reinterpret_cast<const float4*>(x + i);
    __half2* o = reinterpret_cast<__half2*>(g_xh + i);
    o[0] = __floats2half2_rn(v.x, v.y);
    o[1] = __floats2half2_rn(v.z, v.w);
}

// ---------------------------------------------------------------------------
// Kernel 1: gemm1 (x @ Wgu) + fused SiLU-gate, in-loop dequant, pipelined.
// BM=128 x BN=64 pairs (gate n0..+63, up I_+n0..), BK=32, double-buffered.
// 8 warps (wm 0..1 x wn 0..3), warp tile 64x16 gate + 64x16 up (R1-verified).
// Smem: 2 x (As 128x40 + Bg 64x40 + Bu 64x40) halves = 40,960 B static.
// ---------------------------------------------------------------------------
__global__ void __launch_bounds__(256) gemm1_silu_kernel(
    const int*   __restrict__ gup,     // [E, H/2, 2I] int32 (1 byte each)
    const float* __restrict__ gus,     // [E, H/16, 2I]
    const float* __restrict__ pgs)     // scalar gscale
{
    const int e   = blockIdx.z;
    const int bm0 = blockIdx.x * 128;   // m-tile fastest -> weight L2 reuse
    const int n0  = blockIdx.y * 64;
    const float gscale = __ldg(pgs);

    const int tid  = threadIdx.x;
    const int lane = tid & 31;
    const int wid  = tid >> 5;
    const int g    = lane >> 2;
    const int tg   = lane & 3;
    const int wm   = wid & 1;
    const int wn   = wid >> 1;

    __shared__ __half As[2][128 * STR];
    __shared__ __half Bg[2][64 * STR];
    __shared__ __half Bu[2][64 * STR];

    float accg[4][2][4], accu[4][2][4];
#pragma unroll
    for (int a = 0; a < 4; a++)
#pragma unroll
        for (int b = 0; b < 2; b++)
#pragma unroll
            for (int c = 0; c < 4; c++) { accg[a][b][c] = 0.f; accu[a][b][c] = 0.f; }

    const __half* xg = g_xh + (size_t)(e * T_ + bm0) * H_;

    // B loader thread mapping: col = tid&63, oct = (tid>>6)&1, gu = tid>>7.
    // Each thread: one 8-packed-row octet (= one 16-k scale block), 8 LDG + 1 scale.
    const int bcol = tid & 63;
    const int boct = (tid >> 6) & 1;
    const int bgu  = tid >> 7;
    const int bncol = n0 + bcol + (bgu ? I_ : 0);   // column in packed N-dim
    __half* const bdst = (bgu ? Bu[0] : Bg[0]);     // buffer 0 base; buffer1 = +64*STR... 
    // NOTE: use explicit arrays instead (indexed below).

    int   pv[8];
    float bscale;

    auto loadB = [&](int k0) {
        const int kp0 = (k0 >> 1) + boct * 8;       // first packed row
        const int* p = gup + ((size_t)e * (H_ / 2) + kp0) * (2 * I_) + bncol;
#pragma unroll
        for (int j = 0; j < 8; j++) pv[j] = __ldg(p + (size_t)j * (2 * I_));
        bscale = __ldg(gus + ((size_t)e * (H_ / 16) + (kp0 >> 3)) * (2 * I_) + bncol) * gscale;
    };
    auto stsB = [&](int s) {
        __half* d = (bgu ? Bu[s] : Bg[s]) + bcol * STR + 2 * (boct * 8);
#pragma unroll
        for (int j = 0; j < 8; j++)
            *reinterpret_cast<uint32_t*>(d + 2 * j) =
                pack2(fp4f(pv[j] & 15) * bscale, fp4f((pv[j] >> 4) & 15) * bscale);
    };
    auto loadA = [&](int s, int k0) {
#pragma unroll
        for (int i = 0; i < 2; i++) {
            const int u = tid + 256 * i;            // 0..511
            const int row = u >> 2, seg = (u & 3) * 8;
            cpasync16(As[s] + row * STR + seg, xg + (size_t)row * H_ + k0 + seg);
        }
    };

    // prologue
    loadB(0);
    loadA(0, 0);
    CP_COMMIT();
    stsB(0);
    CP_WAIT0();
    __syncthreads();

    const int NIT = H_ / 32;
    int s = 0;
    for (int it = 0; it < NIT; it++) {
        const bool more = (it + 1 < NIT);
        if (more) { loadB((it + 1) * 32); loadA(s ^ 1, (it + 1) * 32); }
        CP_COMMIT();

        // ---- compute: 2 k16 steps (R1-verified fragment scheme, stride STR) ----
#pragma unroll
        for (int kk = 0; kk < 2; kk++) {
            const int cc = kk * 16 + 2 * tg;
            uint32_t a[4][4];
#pragma unroll
            for (int mi = 0; mi < 4; mi++) {
                const int r = wm * 64 + mi * 16 + g;
                a[mi][0] = *reinterpret_cast<const uint32_t*>(As[s] + r * STR + cc);
                a[mi][1] = *reinterpret_cast<const uint32_t*>(As[s] + (r + 8) * STR + cc);
                a[mi][2] = *reinterpret_cast<const uint32_t*>(As[s] + r * STR + cc + 8);
                a[mi][3] = *reinterpret_cast<const uint32_t*>(As[s] + (r + 8) * STR + cc + 8);
            }
#pragma unroll
            for (int ni = 0; ni < 2; ni++) {
                const int nb = wn * 16 + ni * 8 + g;
                const uint32_t bg0 = *reinterpret_cast<const uint32_t*>(Bg[s] + nb * STR + cc);
                const uint32_t bg1 = *reinterpret_cast<const uint32_t*>(Bg[s] + nb * STR + cc + 8);
                const uint32_t bu0 = *reinterpret_cast<const uint32_t*>(Bu[s] + nb * STR + cc);
                const uint32_t bu1 = *reinterpret_cast<const uint32_t*>(Bu[s] + nb * STR + cc + 8);
#pragma unroll
                for (int mi = 0; mi < 4; mi++) {
                    mma16816(accg[mi][ni][0], accg[mi][ni][1], accg[mi][ni][2], accg[mi][ni][3],
                             a[mi][0], a[mi][1], a[mi][2], a[mi][3], bg0, bg1);
                    mma16816(accu[mi][ni][0], accu[mi][ni][1], accu[mi][ni][2], accu[mi][ni][3],
                             a[mi][0], a[mi][1], a[mi][2], a[mi][3], bu0, bu1);
                }
            }
        }

        if (more) stsB(s ^ 1);
        CP_WAIT0();
        __syncthreads();
        s ^= 1;
    }

    // ---- epilogue (verbatim R1): inter = up * silu(gate) ----
#pragma unroll
    for (int mi = 0; mi < 4; mi++) {
        const int r0 = bm0 + wm * 64 + mi * 16 + g;
#pragma unroll
        for (int ni = 0; ni < 2; ni++) {
            const int c0 = n0 + wn * 16 + ni * 8 + 2 * tg;
            const float i0 = accu[mi][ni][0] * silu_f(accg[mi][ni][0]);
            const float i1 = accu[mi][ni][1] * silu_f(accg[mi][ni][1]);
            const float i2 = accu[mi][ni][2] * silu_f(accg[mi][ni][2]);
            const float i3 = accu[mi][ni][3] * silu_f(accg[mi][ni][3]);
            *reinterpret_cast<__half2*>(g_inter + (size_t)(e * T_ + r0) * I_ + c0)
                = __floats2half2_rn(i0, i1);
            *reinterpret_cast<__half2*>(g_inter + (size_t)(e * T_ + r0 + 8) * I_ + c0)
                = __floats2half2_rn(i2, i3);
        }
    }
}

// ---------------------------------------------------------------------------
// Kernel 2: gemm2 (inter @ Wd) -> fp32, in-loop dequant, pipelined.
// BM=128 x BN=128, BK=32, double-buffered. Warp tile 64x32 (R1-verified).
// Smem: 2 x (As 128x40 + Bs 128x40) halves = 40,960 B static.
// ---------------------------------------------------------------------------
__global__ void __launch_bounds__(256) gemm2_kernel(
    const int*   __restrict__ dpk,     // [E, I/2, H] int32
    const float* __restrict__ dsc,     // [E, I/16, H]
    const float* __restrict__ pgs,
    float*       __restrict__ out)     // [E*T, H]
{
    const int e   = blockIdx.z;
    const int bm0 = blockIdx.x * 128;
    const int n0  = blockIdx.y * 128;
    const float gscale = __ldg(pgs);

    const int tid  = threadIdx.x;
    const int lane = tid & 31;
    const int wid  = tid >> 5;
    const int g    = lane >> 2;
    const int tg   = lane & 3;
    const int wm   = wid & 1;
    const int wn   = wid >> 1;

    __shared__ __half As[2][128 * STR];
    __shared__ __half Bs[2][128 * STR];

    float acc[4][4][4];
#pragma unroll
    for (int a = 0; a < 4; a++)
#pragma unroll
        for (int b = 0; b < 4; b++)
#pragma unroll
            for (int c = 0; c < 4; c++) acc[a][b][c] = 0.f;

    const __half* ag = g_inter + (size_t)(e * T_ + bm0) * I_;

    // B loader: col = tid&127, oct = tid>>7 (0..1); 8 packed rows each.
    const int bcol = tid & 127;
    const int boct = tid >> 7;

    int   pv[8];
    float bscale;

    auto loadB = [&](int k0) {
        const int kp0 = (k0 >> 1) + boct * 8;
        const int* p = dpk + ((size_t)e * (I_ / 2) + kp0) * H_ + n0 + bcol;
#pragma unroll
        for (int j = 0; j < 8; j++) pv[j] = __ldg(p + (size_t)j * H_);
        bscale = __ldg(dsc + ((size_t)e * (I_ / 16) + (kp0 >> 3)) * H_ + n0 + bcol) * gscale;
    };
    auto stsB = [&](int s) {
        __half* d = Bs[s] + bcol * STR + 2 * (boct * 8);
#pragma unroll
        for (int j = 0; j < 8; j++)
            *reinterpret_cast<uint32_t*>(d + 2 * j) =
                pack2(fp4f(pv[j] & 15) * bscale, fp4f((pv[j] >> 4) & 15) * bscale);
    };
    auto loadA = [&](int s, int k0) {
#pragma unroll
        for (int i = 0; i < 2; i++) {
            const int u = tid + 256 * i;
            const int row = u >> 2, seg = (u & 3) * 8;
            cpasync16(As[s] + row * STR + seg, ag + (size_t)row * I_ + k0 + seg);
        }
    };

    loadB(0);
    loadA(0, 0);
    CP_COMMIT();
    stsB(0);
    CP_WAIT0();
    __syncthreads();

    const int NIT = I_ / 32;
    int s = 0;
    for (int it = 0; it < NIT; it++) {
        const bool more = (it + 1 < NIT);
        if (more) { loadB((it + 1) * 32); loadA(s ^ 1, (it + 1) * 32); }
        CP_COMMIT();

#pragma unroll
        for (int kk = 0; kk < 2; kk++) {
            const int cc = kk * 16 + 2 * tg;
            uint32_t a[4][4];
#pragma unroll
            for (int mi = 0; mi < 4; mi++) {
                const int r = wm * 64 + mi * 16 + g;
                a[mi][0] = *reinterpret_cast<const uint32_t*>(As[s] + r * STR + cc);
                a[mi][1] = *reinterpret_cast<const uint32_t*>(As[s] + (r + 8) * STR + cc);
                a[mi][2] = *reinterpret_cast<const uint32_t*>(As[s] + r * STR + cc + 8);
                a[mi][3] = *reinterpret_cast<const uint32_t*>(As[s] + (r + 8) * STR + cc + 8);
            }
#pragma unroll
            for (int ni = 0; ni < 4; ni++) {
                const int nb = wn * 32 + ni * 8 + g;
                const uint32_t b0 = *reinterpret_cast<const uint32_t*>(Bs[s] + nb * STR + cc);
                const uint32_t b1 = *reinterpret_cast<const uint32_t*>(Bs[s] + nb * STR + cc + 8);
#pragma unroll
                for (int mi = 0; mi < 4; mi++) {
                    mma16816(acc[mi][ni][0], acc[mi][ni][1], acc[mi][ni][2], acc[mi][ni][3],
                             a[mi][0], a[mi][1], a[mi][2], a[mi][3], b0, b1);
                }
            }
        }

        if (more) stsB(s ^ 1);
        CP_WAIT0();
        __syncthreads();
        s ^= 1;
    }

    // ---- epilogue (verbatim R1) ----
#pragma unroll
    for (int mi = 0; mi < 4; mi++) {
        const int r0 = bm0 + wm * 64 + mi * 16 + g;
#pragma unroll
        for (int ni = 0; ni < 4; ni++) {
            const int c0 = n0 + wn * 32 + ni * 8 + 2 * tg;
            *reinterpret_cast<float2*>(out + (size_t)(e * T_ + r0) * H_ + c0)
                = make_float2(acc[mi][ni][0], acc[mi][ni][1]);
            *reinterpret_cast<float2*>(out + (size_t)(e * T_ + r0 + 8) * H_ + c0)
                = make_float2(acc[mi][ni][2], acc[mi][ni][3]);
        }
    }
}

// ---------------------------------------------------------------------------
// Launch
// ---------------------------------------------------------------------------
extern "C" void kernel_launch(void* const* d_in, const int* in_sizes, int n_in,
                              void* d_out, int out_size) {
    const float* x   = (const float*)d_in[0];
    const int*   gup = (const int*)  d_in[1];
    const float* gus = (const float*)d_in[2];
    const float* gug = (const float*)d_in[3];
    const int*   dpk = (const int*)  d_in[4];
    const float* dsc = (const float*)d_in[5];
    const float* dgs = (const float*)d_in[6];
    float* out = (float*)d_out;

    convert_x_kernel<<<(E_ * T_ * H_) / 1024, 256>>>(x);

    // m-tile fastest (x) -> the 8 m-blocks sharing a weight slab co-resident
    gemm1_silu_kernel<<<dim3(T_ / 128, I_ / 64, E_), 256>>>(gup, gus, gug);
    gemm2_kernel<<<dim3(T_ / 128, H_ / 128, E_), 256>>>(dpk, dsc, dgs, out);
}

// round 7
// speedup vs baseline: 1.9835x; 1.1193x over previous
#include <cuda_runtime.h>
#include <cuda_fp16.h>
#include <cstdint>

#define E_ 8
#define H_ 2048
#define I_ 4096
#define T_ 1024

// ---------------- scratch: 96 MB total — proven static footprint ------------
__device__ __half g_xh[(size_t)E_ * T_ * H_];        // fp16 activations  (32 MB)
__device__ __half g_inter[(size_t)E_ * T_ * I_];     // fp16 intermediate (64 MB)

// ---------------- helpers ----------------
// Exact e2m1 decode: codes 0..7 -> {0,.5,1,1.5,2,3,4,6}, bit3 = sign.
__device__ __forceinline__ float fp4f(int c) {
    int h = c & 7;
    int bits = (h < 2) ? h * 0x3F000000 : (((126 + (h >> 1)) << 23) | ((h & 1) << 22));
    bits |= (c & 8) << 28;
    return __int_as_float(bits);
}

__device__ __forceinline__ uint32_t pack2(float a, float b) {
    __half2 t = __floats2half2_rn(a, b);
    return *reinterpret_cast<uint32_t*>(&t);
}

__device__ __forceinline__ void cpasync16(__half* dst, const __half* src) {
    uint32_t d = (uint32_t)__cvta_generic_to_shared(dst);
    asm volatile("cp.async.cg.shared.global [%0], [%1], 16;" :: "r"(d), "l"(src));
}
#define CP_COMMIT() asm volatile("cp.async.commit_group;")
#define CP_WAIT0()  asm volatile("cp.async.wait_group 0;")

#define LDSM4(d0,d1,d2,d3,ptr) \
    asm volatile("ldmatrix.sync.aligned.m8n8.x4.shared.b16 {%0,%1,%2,%3},[%4];" \
        : "=r"(d0),"=r"(d1),"=r"(d2),"=r"(d3) : "r"(ptr))

__device__ __forceinline__ void mma16816(float& d0, float& d1, float& d2, float& d3,
                                         uint32_t a0, uint32_t a1, uint32_t a2, uint32_t a3,
                                         uint32_t b0, uint32_t b1) {
    asm volatile(
        "mma.sync.aligned.m16n8k16.row.col.f32.f16.f16.f32 "
        "{%0,%1,%2,%3},{%4,%5,%6,%7},{%8,%9},{%0,%1,%2,%3};\n"
        : "+f"(d0), "+f"(d1), "+f"(d2), "+f"(d3)
        : "r"(a0), "r"(a1), "r"(a2), "r"(a3), "r"(b0), "r"(b1));
}

__device__ __forceinline__ float silu_f(float v) { return v / (1.f + __expf(-v)); }

// smem row stride in halves (80 B): row offsets mod 128B are 8 distinct 16B
// segments -> conflict-free for ldmatrix / STS.128.
#define STR 40

// ---------------------------------------------------------------------------
// Kernel 0: fp32 -> fp16 activation convert (verbatim, passing)
// ---------------------------------------------------------------------------
__global__ void convert_x_kernel(const float* __restrict__ x) {
    int i = (blockIdx.x * blockDim.x + threadIdx.x) * 4;
    float4 v = *reinterpret_cast<const float4*>(x + i);
    __half2* o = reinterpret_cast<__half2*>(g_xh + i);
    o[0] = __floats2half2_rn(v.x, v.y);
    o[1] = __floats2half2_rn(v.z, v.w);
}

// ---------------------------------------------------------------------------
// Kernel 1: gemm1 (x @ Wgu) + fused SiLU-gate, in-loop dequant, pipelined.
// BM=128 x BN=64 pairs, BK=32, double-buffered; ldmatrix fragment loads.
// ---------------------------------------------------------------------------
__global__ void __launch_bounds__(256) gemm1_silu_kernel(
    const int*   __restrict__ gup,     // [E, H/2, 2I] int32 (1 byte each)
    const float* __restrict__ gus,     // [E, H/16, 2I]
    const float* __restrict__ pgs)     // scalar gscale
{
    const int e   = blockIdx.z;
    const int bm0 = blockIdx.x * 128;   // m-tile fastest -> weight L2 reuse
    const int n0  = blockIdx.y * 64;
    const float gscale = __ldg(pgs);

    const int tid  = threadIdx.x;
    const int lane = tid & 31;
    const int wid  = tid >> 5;
    const int g    = lane >> 2;
    const int tg   = lane & 3;
    const int wm   = wid & 1;
    const int wn   = wid >> 1;

    __shared__ __half As[2][128 * STR];
    __shared__ __half Bg[2][64 * STR];
    __shared__ __half Bu[2][64 * STR];

    float accg[4][2][4], accu[4][2][4];
#pragma unroll
    for (int a = 0; a < 4; a++)
#pragma unroll
        for (int b = 0; b < 2; b++)
#pragma unroll
            for (int c = 0; c < 4; c++) { accg[a][b][c] = 0.f; accu[a][b][c] = 0.f; }

    const __half* xg = g_xh + (size_t)(e * T_ + bm0) * H_;

    // ldmatrix lane addressing (derived from PTX fragment spec)
    const int a_r = wm * 64 + (lane & 15);
    const int a_c = (lane >> 4) * 8;
    const int b_r = (lane & 7) + ((lane >> 4) << 3);
    const int b_c = ((lane >> 3) & 1) * 8;

    // B loader: col = tid&63, oct = (tid>>6)&1 (one 16-k scale block), gu = tid>>7
    const int bcol = tid & 63;
    const int boct = (tid >> 6) & 1;
    const int bgu  = tid >> 7;
    const int bncol = n0 + bcol + (bgu ? I_ : 0);

    int   pv[8];
    float bscale;

    auto loadB = [&](int k0) {
        const int kp0 = (k0 >> 1) + boct * 8;
        const int* p = gup + ((size_t)e * (H_ / 2) + kp0) * (2 * I_) + bncol;
#pragma unroll
        for (int j = 0; j < 8; j++) pv[j] = __ldg(p + (size_t)j * (2 * I_));
        bscale = __ldg(gus + ((size_t)e * (H_ / 16) + (kp0 >> 3)) * (2 * I_) + bncol) * gscale;
    };
    auto stsB = [&](int s) {
        uint32_t w[8];
#pragma unroll
        for (int j = 0; j < 8; j++)
            w[j] = pack2(fp4f(pv[j] & 15) * bscale, fp4f((pv[j] >> 4) & 15) * bscale);
        __half* d = (bgu ? Bu[s] : Bg[s]) + bcol * STR + 2 * (boct * 8);
        reinterpret_cast<uint4*>(d)[0] = make_uint4(w[0], w[1], w[2], w[3]);
        reinterpret_cast<uint4*>(d)[1] = make_uint4(w[4], w[5], w[6], w[7]);
    };
    auto loadA = [&](int s, int k0) {
#pragma unroll
        for (int i = 0; i < 2; i++) {
            const int u = tid + 256 * i;            // 0..511
            const int row = u >> 2, seg = (u & 3) * 8;
            cpasync16(As[s] + row * STR + seg, xg + (size_t)row * H_ + k0 + seg);
        }
    };

    // prologue
    loadB(0);
    loadA(0, 0);
    CP_COMMIT();
    stsB(0);
    CP_WAIT0();
    __syncthreads();

    const int NIT = H_ / 32;
    int s = 0;
    for (int it = 0; it < NIT; it++) {
        const bool more = (it + 1 < NIT);
        if (more) { loadB((it + 1) * 32); loadA(s ^ 1, (it + 1) * 32); }
        CP_COMMIT();

        // ---- compute: 2 k16 steps, ldmatrix fragments ----
#pragma unroll
        for (int kk = 0; kk < 2; kk++) {
            uint32_t a[4][4];
#pragma unroll
            for (int mi = 0; mi < 4; mi++) {
                uint32_t p = (uint32_t)__cvta_generic_to_shared(
                    As[s] + (a_r + mi * 16) * STR + kk * 16 + a_c);
                LDSM4(a[mi][0], a[mi][1], a[mi][2], a[mi][3], p);
            }
            uint32_t bg[4], bu[4];
            {
                uint32_t pg = (uint32_t)__cvta_generic_to_shared(
                    Bg[s] + (wn * 16 + b_r) * STR + kk * 16 + b_c);
                LDSM4(bg[0], bg[1], bg[2], bg[3], pg);
                uint32_t pu = (uint32_t)__cvta_generic_to_shared(
                    Bu[s] + (wn * 16 + b_r) * STR + kk * 16 + b_c);
                LDSM4(bu[0], bu[1], bu[2], bu[3], pu);
            }
#pragma unroll
            for (int ni = 0; ni < 2; ni++) {
#pragma unroll
                for (int mi = 0; mi < 4; mi++) {
                    mma16816(accg[mi][ni][0], accg[mi][ni][1], accg[mi][ni][2], accg[mi][ni][3],
                             a[mi][0], a[mi][1], a[mi][2], a[mi][3],
                             bg[2 * ni], bg[2 * ni + 1]);
                    mma16816(accu[mi][ni][0], accu[mi][ni][1], accu[mi][ni][2], accu[mi][ni][3],
                             a[mi][0], a[mi][1], a[mi][2], a[mi][3],
                             bu[2 * ni], bu[2 * ni + 1]);
                }
            }
        }

        if (more) stsB(s ^ 1);
        CP_WAIT0();
        __syncthreads();
        s ^= 1;
    }

    // ---- epilogue: inter = up * silu(gate) ----
#pragma unroll
    for (int mi = 0; mi < 4; mi++) {
        const int r0 = bm0 + wm * 64 + mi * 16 + g;
#pragma unroll
        for (int ni = 0; ni < 2; ni++) {
            const int c0 = n0 + wn * 16 + ni * 8 + 2 * tg;
            const float i0 = accu[mi][ni][0] * silu_f(accg[mi][ni][0]);
            const float i1 = accu[mi][ni][1] * silu_f(accg[mi][ni][1]);
            const float i2 = accu[mi][ni][2] * silu_f(accg[mi][ni][2]);
            const float i3 = accu[mi][ni][3] * silu_f(accg[mi][ni][3]);
            *reinterpret_cast<__half2*>(g_inter + (size_t)(e * T_ + r0) * I_ + c0)
                = __floats2half2_rn(i0, i1);
            *reinterpret_cast<__half2*>(g_inter + (size_t)(e * T_ + r0 + 8) * I_ + c0)
                = __floats2half2_rn(i2, i3);
        }
    }
}

// ---------------------------------------------------------------------------
// Kernel 2: gemm2 (inter @ Wd) -> fp32, in-loop dequant, pipelined, ldmatrix.
// BM=128 x BN=128, BK=32, double-buffered. Warp tile 64x32.
// ---------------------------------------------------------------------------
__global__ void __launch_bounds__(256) gemm2_kernel(
    const int*   __restrict__ dpk,     // [E, I/2, H] int32
    const float* __restrict__ dsc,     // [E, I/16, H]
    const float* __restrict__ pgs,
    float*       __restrict__ out)     // [E*T, H]
{
    const int e   = blockIdx.z;
    const int bm0 = blockIdx.x * 128;
    const int n0  = blockIdx.y * 128;
    const float gscale = __ldg(pgs);

    const int tid  = threadIdx.x;
    const int lane = tid & 31;
    const int wid  = tid >> 5;
    const int g    = lane >> 2;
    const int tg   = lane & 3;
    const int wm   = wid & 1;
    const int wn   = wid >> 1;

    __shared__ __half As[2][128 * STR];
    __shared__ __half Bs[2][128 * STR];

    float acc[4][4][4];
#pragma unroll
    for (int a = 0; a < 4; a++)
#pragma unroll
        for (int b = 0; b < 4; b++)
#pragma unroll
            for (int c = 0; c < 4; c++) acc[a][b][c] = 0.f;

    const __half* ag = g_inter + (size_t)(e * T_ + bm0) * I_;

    const int a_r = wm * 64 + (lane & 15);
    const int a_c = (lane >> 4) * 8;
    const int b_r = (lane & 7) + ((lane >> 4) << 3);
    const int b_c = ((lane >> 3) & 1) * 8;

    // B loader: col = tid&127, oct = tid>>7 (0..1)
    const int bcol = tid & 127;
    const int boct = tid >> 7;

    int   pv[8];
    float bscale;

    auto loadB = [&](int k0) {
        const int kp0 = (k0 >> 1) + boct * 8;
        const int* p = dpk + ((size_t)e * (I_ / 2) + kp0) * H_ + n0 + bcol;
#pragma unroll
        for (int j = 0; j < 8; j++) pv[j] = __ldg(p + (size_t)j * H_);
        bscale = __ldg(dsc + ((size_t)e * (I_ / 16) + (kp0 >> 3)) * H_ + n0 + bcol) * gscale;
    };
    auto stsB = [&](int s) {
        uint32_t w[8];
#pragma unroll
        for (int j = 0; j < 8; j++)
            w[j] = pack2(fp4f(pv[j] & 15) * bscale, fp4f((pv[j] >> 4) & 15) * bscale);
        __half* d = Bs[s] + bcol * STR + 2 * (boct * 8);
        reinterpret_cast<uint4*>(d)[0] = make_uint4(w[0], w[1], w[2], w[3]);
        reinterpret_cast<uint4*>(d)[1] = make_uint4(w[4], w[5], w[6], w[7]);
    };
    auto loadA = [&](int s, int k0) {
#pragma unroll
        for (int i = 0; i < 2; i++) {
            const int u = tid + 256 * i;
            const int row = u >> 2, seg = (u & 3) * 8;
            cpasync16(As[s] + row * STR + seg, ag + (size_t)row * I_ + k0 + seg);
        }
    };

    loadB(0);
    loadA(0, 0);
    CP_COMMIT();
    stsB(0);
    CP_WAIT0();
    __syncthreads();

    const int NIT = I_ / 32;
    int s = 0;
    for (int it = 0; it < NIT; it++) {
        const bool more = (it + 1 < NIT);
        if (more) { loadB((it + 1) * 32); loadA(s ^ 1, (it + 1) * 32); }
        CP_COMMIT();

#pragma unroll
        for (int kk = 0; kk < 2; kk++) {
            uint32_t a[4][4];
#pragma unroll
            for (int mi = 0; mi < 4; mi++) {
                uint32_t p = (uint32_t)__cvta_generic_to_shared(
                    As[s] + (a_r + mi * 16) * STR + kk * 16 + a_c);
                LDSM4(a[mi][0], a[mi][1], a[mi][2], a[mi][3], p);
            }
            uint32_t bq[2][4];
#pragma unroll
            for (int h = 0; h < 2; h++) {
                uint32_t p = (uint32_t)__cvta_generic_to_shared(
                    Bs[s] + (wn * 32 + h * 16 + b_r) * STR + kk * 16 + b_c);
                LDSM4(bq[h][0], bq[h][1], bq[h][2], bq[h][3], p);
            }
#pragma unroll
            for (int ni = 0; ni < 4; ni++) {
                const uint32_t b0 = bq[ni >> 1][2 * (ni & 1)];
                const uint32_t b1 = bq[ni >> 1][2 * (ni & 1) + 1];
#pragma unroll
                for (int mi = 0; mi < 4; mi++) {
                    mma16816(acc[mi][ni][0], acc[mi][ni][1], acc[mi][ni][2], acc[mi][ni][3],
                             a[mi][0], a[mi][1], a[mi][2], a[mi][3], b0, b1);
                }
            }
        }

        if (more) stsB(s ^ 1);
        CP_WAIT0();
        __syncthreads();
        s ^= 1;
    }

    // ---- epilogue ----
#pragma unroll
    for (int mi = 0; mi < 4; mi++) {
        const int r0 = bm0 + wm * 64 + mi * 16 + g;
#pragma unroll
        for (int ni = 0; ni < 4; ni++) {
            const int c0 = n0 + wn * 32 + ni * 8 + 2 * tg;
            *reinterpret_cast<float2*>(out + (size_t)(e * T_ + r0) * H_ + c0)
                = make_float2(acc[mi][ni][0], acc[mi][ni][1]);
            *reinterpret_cast<float2*>(out + (size_t)(e * T_ + r0 + 8) * H_ + c0)
                = make_float2(acc[mi][ni][2], acc[mi][ni][3]);
        }
    }
}

// ---------------------------------------------------------------------------
// Launch
// ---------------------------------------------------------------------------
extern "C" void kernel_launch(void* const* d_in, const int* in_sizes, int n_in,
                              void* d_out, int out_size) {
    const float* x   = (const float*)d_in[0];
    const int*   gup = (const int*)  d_in[1];
    const float* gus = (const float*)d_in[2];
    const float* gug = (const float*)d_in[3];
    const int*   dpk = (const int*)  d_in[4];
    const float* dsc = (const float*)d_in[5];
    const float* dgs = (const float*)d_in[6];
    float* out = (float*)d_out;

    convert_x_kernel<<<(E_ * T_ * H_) / 1024, 256>>>(x);

    gemm1_silu_kernel<<<dim3(T_ / 128, I_ / 64, E_), 256>>>(gup, gus, gug);
    gemm2_kernel<<<dim3(T_ / 128, H_ / 128, E_), 256>>>(dpk, dsc, dgs, out);
}